// round 1
// baseline (speedup 1.0000x reference)
#include <cuda_runtime.h>
#include <math.h>

#define Nn 50000
#define Rr 4
#define Ee 1600000
#define Hh 256
#define Cc 16

// ---------------- scratch (device globals; no runtime allocation) ----------
__device__ int   g_deg_r[Rr * Nn];
__device__ int   g_deg_c[Rr * Nn];
__device__ float g_dinv_r[Rr * Nn];
__device__ float g_dinv_c[Rr * Nn];
__device__ int   g_row_ptr[Rr * (Nn + 1)];
__device__ int   g_cursor[Rr * Nn];
__device__ int   g_cols[Rr * Ee];       // CSR column indices (per relation)
__device__ float g_wgt[Rr * Ee];        // CSR edge weights dinv_r*dinv_c
__device__ float g_S[(size_t)Rr * Nn * Hh];  // SpMM outputs per relation
__device__ float g_H[(size_t)Rr * Nn * Hh];  // ReLU(S @ W) per relation
__device__ float g_h1[(size_t)Nn * Hh];      // layer-1 mean

// ---------------- CSR construction -----------------------------------------
__global__ void k_zero_deg() {
    int i = blockIdx.x * blockDim.x + threadIdx.x;
    if (i < Rr * Nn) { g_deg_r[i] = 0; g_deg_c[i] = 0; }
}

__global__ void k_hist(const int* __restrict__ ei) {
    int idx = blockIdx.x * blockDim.x + threadIdx.x;
    if (idx >= Rr * Ee) return;
    int r = idx / Ee, e = idx - r * Ee;
    const int* base = ei + (size_t)r * 2 * Ee;
    atomicAdd(&g_deg_r[r * Nn + base[e]], 1);
    atomicAdd(&g_deg_c[r * Nn + base[Ee + e]], 1);
}

__global__ void k_dinv() {
    int i = blockIdx.x * blockDim.x + threadIdx.x;
    if (i >= Rr * Nn) return;
    g_dinv_r[i] = rsqrtf(fmaxf((float)g_deg_r[i], 1.0f));
    g_dinv_c[i] = rsqrtf(fmaxf((float)g_deg_c[i], 1.0f));
}

// one block per relation: exclusive scan of deg_r -> row_ptr (+ cursor init)
__global__ void k_scan() {
    int r = blockIdx.x;
    __shared__ int sh[1024];
    int t = threadIdx.x;
    int carry = 0;
    for (int base = 0; base < Nn; base += 1024) {
        int i = base + t;
        int v = (i < Nn) ? g_deg_r[r * Nn + i] : 0;
        sh[t] = v;
        __syncthreads();
        for (int off = 1; off < 1024; off <<= 1) {
            int x = (t >= off) ? sh[t - off] : 0;
            __syncthreads();
            sh[t] += x;
            __syncthreads();
        }
        int incl = sh[t];
        int total = sh[1023];
        if (i < Nn) {
            int excl = incl - v + carry;
            g_row_ptr[r * (Nn + 1) + i] = excl;
            g_cursor[r * Nn + i] = excl;
        }
        carry += total;
        __syncthreads();
    }
    if (t == 0) g_row_ptr[r * (Nn + 1) + Nn] = carry;
}

__global__ void k_scatter(const int* __restrict__ ei) {
    int idx = blockIdx.x * blockDim.x + threadIdx.x;
    if (idx >= Rr * Ee) return;
    int r = idx / Ee, e = idx - r * Ee;
    const int* base = ei + (size_t)r * 2 * Ee;
    int row = base[e];
    int col = base[Ee + e];
    int pos = atomicAdd(&g_cursor[r * Nn + row], 1);
    size_t o = (size_t)r * Ee + pos;
    g_cols[o] = col;
    g_wgt[o] = g_dinv_r[r * Nn + row] * g_dinv_c[r * Nn + col];
}

// ---------------- SpMM: S[r] = Ahat_r @ src  (warp per row) ----------------
__global__ __launch_bounds__(256) void k_spmm(const float* __restrict__ xsrc, int use_h1) {
    int r = blockIdx.y;
    int n = blockIdx.x * 8 + (threadIdx.x >> 5);
    if (n >= Nn) return;
    int lane = threadIdx.x & 31;
    const float* src = use_h1 ? (const float*)g_h1 : xsrc;
    int beg = g_row_ptr[r * (Nn + 1) + n];
    int end = g_row_ptr[r * (Nn + 1) + n + 1];
    const int*   cols = g_cols + (size_t)r * Ee;
    const float* ws   = g_wgt  + (size_t)r * Ee;
    float4 a0 = make_float4(0.f, 0.f, 0.f, 0.f);
    float4 a1 = make_float4(0.f, 0.f, 0.f, 0.f);
    for (int e = beg; e < end; ++e) {
        int c = cols[e];
        float w = ws[e];
        const float4* s4 = (const float4*)(src + (size_t)c * Hh);
        float4 f0 = s4[lane];
        float4 f1 = s4[lane + 32];
        a0.x += w * f0.x; a0.y += w * f0.y; a0.z += w * f0.z; a0.w += w * f0.w;
        a1.x += w * f1.x; a1.y += w * f1.y; a1.z += w * f1.z; a1.w += w * f1.w;
    }
    float4* d4 = (float4*)(g_S + ((size_t)r * Nn + n) * Hh);
    d4[lane]      = a0;
    d4[lane + 32] = a1;
}

// ---------------- GEMM: H[r] = ReLU(S[r] @ W[r])  (128x128x8 SGEMM) --------
__global__ __launch_bounds__(256) void k_gemm(const float* __restrict__ Wall) {
    int r = blockIdx.z;
    const float* Ar = g_S + (size_t)r * Nn * Hh;
    const float* Wr = Wall + (size_t)r * Hh * Hh;
    float*       Or = g_H + (size_t)r * Nn * Hh;
    const int row0 = blockIdx.x * 128;
    const int col0 = blockIdx.y * 128;
    __shared__ float As[8][128];
    __shared__ float Bs[8][128];
    int t = threadIdx.x;
    int aRow = t >> 1;
    int aCol = (t & 1) * 4;
    int bRow = t >> 5;
    int bCol = (t & 31) * 4;
    int ty = t >> 4, tx = t & 15;

    float acc[8][8];
#pragma unroll
    for (int i = 0; i < 8; i++)
#pragma unroll
        for (int j = 0; j < 8; j++) acc[i][j] = 0.f;

    for (int k0 = 0; k0 < Hh; k0 += 8) {
        float4 av = make_float4(0.f, 0.f, 0.f, 0.f);
        int gr = row0 + aRow;
        if (gr < Nn) av = *(const float4*)(Ar + (size_t)gr * Hh + k0 + aCol);
        As[aCol + 0][aRow] = av.x;
        As[aCol + 1][aRow] = av.y;
        As[aCol + 2][aRow] = av.z;
        As[aCol + 3][aRow] = av.w;
        float4 bv = *(const float4*)(Wr + (size_t)(k0 + bRow) * Hh + col0 + bCol);
        *(float4*)&Bs[bRow][bCol] = bv;
        __syncthreads();
#pragma unroll
        for (int k = 0; k < 8; k++) {
            float4 ra0 = *(const float4*)&As[k][ty * 8];
            float4 ra1 = *(const float4*)&As[k][ty * 8 + 4];
            float4 rb0 = *(const float4*)&Bs[k][tx * 8];
            float4 rb1 = *(const float4*)&Bs[k][tx * 8 + 4];
            float ra[8] = {ra0.x, ra0.y, ra0.z, ra0.w, ra1.x, ra1.y, ra1.z, ra1.w};
            float rb[8] = {rb0.x, rb0.y, rb0.z, rb0.w, rb1.x, rb1.y, rb1.z, rb1.w};
#pragma unroll
            for (int i = 0; i < 8; i++)
#pragma unroll
                for (int j = 0; j < 8; j++) acc[i][j] += ra[i] * rb[j];
        }
        __syncthreads();
    }
#pragma unroll
    for (int i = 0; i < 8; i++) {
        int gr = row0 + ty * 8 + i;
        if (gr < Nn) {
            float4 o0, o1;
            o0.x = fmaxf(acc[i][0], 0.f); o0.y = fmaxf(acc[i][1], 0.f);
            o0.z = fmaxf(acc[i][2], 0.f); o0.w = fmaxf(acc[i][3], 0.f);
            o1.x = fmaxf(acc[i][4], 0.f); o1.y = fmaxf(acc[i][5], 0.f);
            o1.z = fmaxf(acc[i][6], 0.f); o1.w = fmaxf(acc[i][7], 0.f);
            float* dst = Or + (size_t)gr * Hh + col0 + tx * 8;
            *(float4*)dst = o0;
            *(float4*)(dst + 4) = o1;
        }
    }
}

// ---------------- layer-1 mean: h1 = 0.25 * sum_r H[r] ---------------------
__global__ void k_mean() {
    int idx = blockIdx.x * blockDim.x + threadIdx.x;
    const int total = Nn * Hh / 4;
    if (idx >= total) return;
    const float4* h = (const float4*)g_H;
    size_t off = (size_t)Nn * Hh / 4;
    float4 a = h[idx], b = h[idx + off], c = h[idx + 2 * off], d = h[idx + 3 * off];
    float4 m;
    m.x = 0.25f * (a.x + b.x + c.x + d.x);
    m.y = 0.25f * (a.y + b.y + c.y + d.y);
    m.z = 0.25f * (a.z + b.z + c.z + d.z);
    m.w = 0.25f * (a.w + b.w + c.w + d.w);
    ((float4*)g_h1)[idx] = m;
}

// ---------------- attention + residual fusion + output GEMM ----------------
__global__ __launch_bounds__(256) void k_attn(const float* __restrict__ att_q,
                                              const float* __restrict__ tau_p,
                                              const float* __restrict__ W_out,
                                              const float* __restrict__ b_out,
                                              float* __restrict__ out) {
    int n = blockIdx.x * 8 + (threadIdx.x >> 5);
    if (n >= Nn) return;
    int lane = threadIdx.x & 31;

    float q[8];
#pragma unroll
    for (int k = 0; k < 8; k++) q[k] = att_q[lane + 32 * k];

    float v[4][8];
    float sc[4];
#pragma unroll
    for (int r = 0; r < 4; r++) {
        const float* h = g_H + ((size_t)r * Nn + n) * Hh;
        float s = 0.f;
#pragma unroll
        for (int k = 0; k < 8; k++) {
            v[r][k] = h[lane + 32 * k];
            s += v[r][k] * q[k];
        }
#pragma unroll
        for (int o = 16; o; o >>= 1) s += __shfl_xor_sync(0xffffffffu, s, o);
        sc[r] = s;
    }
    float tc = fminf(fmaxf(tau_p[0], 0.5f), 5.0f);
    float inv = 1.0f / tc;
    float s0 = sc[0] * inv, s1 = sc[1] * inv, s2 = sc[2] * inv, s3 = sc[3] * inv;
    float m = fmaxf(fmaxf(s0, s1), fmaxf(s2, s3));
    float e0 = expf(s0 - m), e1 = expf(s1 - m), e2 = expf(s2 - m), e3 = expf(s3 - m);
    float se = e0 + e1 + e2 + e3;
    float al[4] = {e0 / se, e1 / se, e2 / se, e3 / se};

    float h2[8];
#pragma unroll
    for (int k = 0; k < 8; k++)
        h2[k] = (0.25f + al[0]) * v[0][k] + (0.25f + al[1]) * v[1][k] +
                (0.25f + al[2]) * v[2][k] + (0.25f + al[3]) * v[3][k];

    float acc[16];
#pragma unroll
    for (int c = 0; c < 16; c++) acc[c] = 0.f;
#pragma unroll
    for (int k = 0; k < 8; k++) {
        int idx = lane + 32 * k;
        const float4* wr = (const float4*)(W_out + (size_t)idx * 16);
        float4 w0 = wr[0], w1 = wr[1], w2 = wr[2], w3 = wr[3];
        float hv = h2[k];
        acc[0]  += hv * w0.x; acc[1]  += hv * w0.y; acc[2]  += hv * w0.z; acc[3]  += hv * w0.w;
        acc[4]  += hv * w1.x; acc[5]  += hv * w1.y; acc[6]  += hv * w1.z; acc[7]  += hv * w1.w;
        acc[8]  += hv * w2.x; acc[9]  += hv * w2.y; acc[10] += hv * w2.z; acc[11] += hv * w2.w;
        acc[12] += hv * w3.x; acc[13] += hv * w3.y; acc[14] += hv * w3.z; acc[15] += hv * w3.w;
    }
#pragma unroll
    for (int c = 0; c < 16; c++)
#pragma unroll
        for (int o = 16; o; o >>= 1) acc[c] += __shfl_xor_sync(0xffffffffu, acc[c], o);

    if (lane < 16) {
        float lg = 0.f;
#pragma unroll
        for (int c = 0; c < 16; c++)
            if (lane == c) lg = acc[c];
        out[(size_t)n * Cc + lane] = lg + b_out[lane];
    }
    if (lane < 4) {
        float a = al[0];
        if (lane == 1) a = al[1];
        if (lane == 2) a = al[2];
        if (lane == 3) a = al[3];
        out[(size_t)Nn * Cc + (size_t)n * Rr + lane] = a;
    }
}

// ---------------- launch ----------------------------------------------------
extern "C" void kernel_launch(void* const* d_in, const int* in_sizes, int n_in,
                              void* d_out, int out_size) {
    const float* X     = (const float*)d_in[0];
    const int*   EI    = (const int*)d_in[1];
    const float* W1    = (const float*)d_in[2];
    const float* W2    = (const float*)d_in[3];
    const float* att_q = (const float*)d_in[4];
    const float* tau   = (const float*)d_in[5];
    const float* W_out = (const float*)d_in[6];
    const float* b_out = (const float*)d_in[7];
    float* out = (float*)d_out;
    (void)in_sizes; (void)n_in; (void)out_size;

    // CSR build (deg -> dinv -> row_ptr -> sorted cols/weights)
    k_zero_deg<<<(Rr * Nn + 255) / 256, 256>>>();
    k_hist<<<(Rr * Ee + 255) / 256, 256>>>(EI);
    k_dinv<<<(Rr * Nn + 255) / 256, 256>>>();
    k_scan<<<Rr, 1024>>>();
    k_scatter<<<(Rr * Ee + 255) / 256, 256>>>(EI);

    dim3 spmm_grid((Nn + 7) / 8, Rr);
    dim3 gemm_grid((Nn + 127) / 128, Hh / 128, Rr);

    // Layer 1
    k_spmm<<<spmm_grid, 256>>>(X, 0);
    k_gemm<<<gemm_grid, 256>>>(W1);
    k_mean<<<(Nn * Hh / 4 + 255) / 256, 256>>>();

    // Layer 2
    k_spmm<<<spmm_grid, 256>>>(X, 1);
    k_gemm<<<gemm_grid, 256>>>(W2);

    // Attention + output head
    k_attn<<<(Nn + 7) / 8, 256>>>(att_q, tau, W_out, b_out, out);
}

// round 4
// speedup vs baseline: 1.4872x; 1.4872x over previous
#include <cuda_runtime.h>
#include <cuda_bf16.h>
#include <cstdint>
#include <math.h>

#define Nn 50000
#define Rr 4
#define Ee 1600000
#define Hh 256
#define Cc 16

// ---------------- scratch (device globals; no runtime allocation) ----------
__device__ int   g_deg_r[Rr * Nn];
__device__ int   g_deg_c[Rr * Nn];
__device__ float g_dinv_r[Rr * Nn];
__device__ float g_dinv_c[Rr * Nn];
__device__ int   g_row_ptr[Rr * (Nn + 1)];
__device__ int   g_cursor[Rr * Nn];
__device__ int   g_cols[Rr * Ee];
__device__ float g_wgt[Rr * Ee];
// bf16 hi/lo split of SpMM outputs: [R][N][256] bf16, 32 uint4 per row
__device__ uint4 g_Shi[(size_t)Rr * Nn * 32];
__device__ uint4 g_Slo[(size_t)Rr * Nn * 32];
// bf16 hi/lo split of W transposed to n-major: [R][n=256][k=256]
__device__ uint4 g_Bhi[Rr * 256 * 32];
__device__ uint4 g_Blo[Rr * 256 * 32];
__device__ float g_H[(size_t)Rr * Nn * Hh];
__device__ float g_h1[(size_t)Nn * Hh];

// ---------------- low-level helpers (all base-arch PTX, no 'a' features) ---
__device__ __forceinline__ uint32_t smem_to_u32(const void* p) {
    uint32_t a;
    asm("{ .reg .u64 t; cvta.to.shared.u64 t, %1; cvt.u32.u64 %0, t; }" : "=r"(a) : "l"(p));
    return a;
}
__device__ __forceinline__ void cp16(uint32_t dst, const void* src, int sz) {
    asm volatile("cp.async.cg.shared.global [%0], [%1], 16, %2;"
                 :: "r"(dst), "l"(src), "r"(sz));
}
__device__ __forceinline__ void ldsm4(uint32_t* r, uint32_t addr) {
    asm volatile("ldmatrix.sync.aligned.m8n8.x4.shared.b16 {%0,%1,%2,%3}, [%4];"
                 : "=r"(r[0]), "=r"(r[1]), "=r"(r[2]), "=r"(r[3]) : "r"(addr));
}
__device__ __forceinline__ void mma16816(float* c, const uint32_t* a, uint32_t b0, uint32_t b1) {
    asm volatile("mma.sync.aligned.m16n8k16.row.col.f32.bf16.bf16.f32 "
                 "{%0,%1,%2,%3}, {%4,%5,%6,%7}, {%8,%9}, {%0,%1,%2,%3};"
                 : "+f"(c[0]), "+f"(c[1]), "+f"(c[2]), "+f"(c[3])
                 : "r"(a[0]), "r"(a[1]), "r"(a[2]), "r"(a[3]), "r"(b0), "r"(b1));
}

// ---------------- bf16 split helpers ----------------------------------------
__device__ __forceinline__ void split2(float x, unsigned short& h, unsigned short& l) {
    __nv_bfloat16 hb = __float2bfloat16(x);
    h = __bfloat16_as_ushort(hb);
    l = __bfloat16_as_ushort(__float2bfloat16(x - __bfloat162float(hb)));
}
__device__ __forceinline__ void split_store4(uint2* hp, uint2* lp, float4 v) {
    unsigned short h0, h1, h2, h3, l0, l1, l2, l3;
    split2(v.x, h0, l0); split2(v.y, h1, l1); split2(v.z, h2, l2); split2(v.w, h3, l3);
    uint2 hv, lv;
    hv.x = (uint32_t)h0 | ((uint32_t)h1 << 16); hv.y = (uint32_t)h2 | ((uint32_t)h3 << 16);
    lv.x = (uint32_t)l0 | ((uint32_t)l1 << 16); lv.y = (uint32_t)l2 | ((uint32_t)l3 << 16);
    *hp = hv; *lp = lv;
}

// ---------------- CSR construction ------------------------------------------
__global__ void k_zero_deg() {
    int i = blockIdx.x * blockDim.x + threadIdx.x;
    if (i < Rr * Nn) { g_deg_r[i] = 0; g_deg_c[i] = 0; }
}
__global__ void k_hist(const int* __restrict__ ei) {
    int idx = blockIdx.x * blockDim.x + threadIdx.x;
    if (idx >= Rr * Ee) return;
    int r = idx / Ee, e = idx - r * Ee;
    const int* base = ei + (size_t)r * 2 * Ee;
    atomicAdd(&g_deg_r[r * Nn + base[e]], 1);
    atomicAdd(&g_deg_c[r * Nn + base[Ee + e]], 1);
}
__global__ void k_dinv() {
    int i = blockIdx.x * blockDim.x + threadIdx.x;
    if (i >= Rr * Nn) return;
    g_dinv_r[i] = rsqrtf(fmaxf((float)g_deg_r[i], 1.0f));
    g_dinv_c[i] = rsqrtf(fmaxf((float)g_deg_c[i], 1.0f));
}
// one block per relation: warp-shuffle exclusive scan
__global__ __launch_bounds__(1024) void k_scan() {
    int r = blockIdx.x;
    __shared__ int wsum[32];
    __shared__ int s_carry;
    int t = threadIdx.x, lane = t & 31, w = t >> 5;
    if (t == 0) s_carry = 0;
    __syncthreads();
    for (int base = 0; base < Nn; base += 1024) {
        int i = base + t;
        int v = (i < Nn) ? g_deg_r[r * Nn + i] : 0;
        int x = v;
#pragma unroll
        for (int o = 1; o < 32; o <<= 1) {
            int y = __shfl_up_sync(0xffffffffu, x, o);
            if (lane >= o) x += y;
        }
        if (lane == 31) wsum[w] = x;
        __syncthreads();
        if (w == 0) {
            int s = wsum[lane];
#pragma unroll
            for (int o = 1; o < 32; o <<= 1) {
                int y = __shfl_up_sync(0xffffffffu, s, o);
                if (lane >= o) s += y;
            }
            wsum[lane] = s;
        }
        __syncthreads();
        int woff = (w == 0) ? 0 : wsum[w - 1];
        int incl = x + woff + s_carry;
        if (i < Nn) {
            g_row_ptr[r * (Nn + 1) + i] = incl - v;
            g_cursor[r * Nn + i] = incl - v;
        }
        __syncthreads();
        if (t == 1023) s_carry = incl;
        __syncthreads();
    }
    if (t == 0) g_row_ptr[r * (Nn + 1) + Nn] = s_carry;
}
__global__ void k_scatter(const int* __restrict__ ei) {
    int idx = blockIdx.x * blockDim.x + threadIdx.x;
    if (idx >= Rr * Ee) return;
    int r = idx / Ee, e = idx - r * Ee;
    const int* base = ei + (size_t)r * 2 * Ee;
    int row = base[e];
    int col = base[Ee + e];
    int pos = atomicAdd(&g_cursor[r * Nn + row], 1);
    size_t o = (size_t)r * Ee + pos;
    g_cols[o] = col;
    g_wgt[o] = g_dinv_r[r * Nn + row] * g_dinv_c[r * Nn + col];
}

// ---------------- SpMM: warp per row, writes bf16 hi/lo splits --------------
__global__ __launch_bounds__(256) void k_spmm(const float* __restrict__ xsrc, int use_h1) {
    int r = blockIdx.y;
    int n = blockIdx.x * 8 + (threadIdx.x >> 5);
    if (n >= Nn) return;
    int lane = threadIdx.x & 31;
    const float* src = use_h1 ? (const float*)g_h1 : xsrc;
    int beg = g_row_ptr[r * (Nn + 1) + n];
    int end = g_row_ptr[r * (Nn + 1) + n + 1];
    const int*   cols = g_cols + (size_t)r * Ee;
    const float* ws   = g_wgt  + (size_t)r * Ee;
    float4 a0 = make_float4(0.f, 0.f, 0.f, 0.f);
    float4 a1 = make_float4(0.f, 0.f, 0.f, 0.f);
    for (int e = beg; e < end; ++e) {
        int c = cols[e];
        float w = ws[e];
        const float4* s4 = (const float4*)(src + (size_t)c * Hh);
        float4 f0 = s4[lane];
        float4 f1 = s4[lane + 32];
        a0.x += w * f0.x; a0.y += w * f0.y; a0.z += w * f0.z; a0.w += w * f0.w;
        a1.x += w * f1.x; a1.y += w * f1.y; a1.z += w * f1.z; a1.w += w * f1.w;
    }
    size_t rb = ((size_t)r * Nn + n) * 64;  // row = 64 uint2
    uint2* hi2 = (uint2*)g_Shi;
    uint2* lo2 = (uint2*)g_Slo;
    split_store4(hi2 + rb + lane,      lo2 + rb + lane,      a0);
    split_store4(hi2 + rb + 32 + lane, lo2 + rb + 32 + lane, a1);
}

// ---------------- W split+transpose: Bhi[r][n][k] = bf16split(W[r][k][n]) ---
__global__ void k_splitW(const float* __restrict__ W) {
    int idx = blockIdx.x * blockDim.x + threadIdx.x;
    if (idx >= Rr * 256 * 256) return;
    int r = idx >> 16;
    int n = (idx >> 8) & 255;
    int k = idx & 255;
    float w = W[((size_t)r << 16) + ((size_t)k << 8) + n];
    unsigned short h, l;
    split2(w, h, l);
    size_t o = ((size_t)r << 16) + ((size_t)n << 8) + k;
    ((unsigned short*)g_Bhi)[o] = h;
    ((unsigned short*)g_Blo)[o] = l;
}

// ---------------- mma.sync GEMM: H[r] = ReLU(S[r] @ W[r]) -------------------
// CTA tile 128x128, K=256 in 4 chunks of 64; cp.async double-buffered A,
// full B (hi/lo) resident in smem; 3-combo bf16 split (hi*hi + hi*lo + lo*hi).
#define A_STRIDE 72                      // bf16 elems per A smem row (64+8 pad)
#define B_STRIDE 264                     // bf16 elems per B smem row (256+8 pad)
#define ASZ (128 * A_STRIDE * 2)         // 18432 B, one A part (hi or lo), one stage
#define SM_B_HI 0
#define SM_B_LO (128 * B_STRIDE * 2)     // 67584
#define SM_A0   (2 * 128 * B_STRIDE * 2) // 135168
#define SMEM_GEMM (SM_A0 + 4 * ASZ)      // 208896

__global__ __launch_bounds__(256) void k_gemm_mma() {
    extern __shared__ char smem[];
    uint32_t sb = smem_to_u32(smem);
    int tid = threadIdx.x, lane = tid & 31, wid = tid >> 5;
    int wm = wid >> 1, wn = wid & 1;                 // 4 m-warps x 2 n-warps
    int r = blockIdx.z, m0 = blockIdx.x * 128, n0 = blockIdx.y * 128;

    // ---- issue B loads (whole 128 x 256 hi+lo) via cp.async --------------
    {
        const uint4* bh = g_Bhi + ((size_t)(r * 256 + n0)) * 32;
        const uint4* bl = g_Blo + ((size_t)(r * 256 + n0)) * 32;
#pragma unroll
        for (int j = 0; j < 16; j++) {
            int lin = tid + j * 256;              // 0..4095
            int row = lin >> 5, ch = lin & 31;
            uint32_t so = row * (B_STRIDE * 2) + ch * 16;
            cp16(sb + SM_B_HI + so, bh + row * 32 + ch, 16);
            cp16(sb + SM_B_LO + so, bl + row * 32 + ch, 16);
        }
    }
    asm volatile("cp.async.commit_group;" ::: "memory");

    // ---- A stage issue helper ---------------------------------------------
    auto issueA = [&](int kc) {
        int s = kc & 1;
        uint32_t abase = sb + SM_A0 + s * 2 * ASZ;
#pragma unroll
        for (int j = 0; j < 4; j++) {
            int lin = tid + j * 256;              // 0..1023
            int row = lin >> 3, ch = lin & 7;
            int gm = m0 + row;
            int sz = (gm < Nn) ? 16 : 0;
            int gmc = (gm < Nn) ? gm : (Nn - 1);
            size_t gi = ((size_t)r * Nn + gmc) * 32 + kc * 8 + ch;
            uint32_t so = row * (A_STRIDE * 2) + ch * 16;
            cp16(abase + so, g_Shi + gi, sz);
            cp16(abase + ASZ + so, g_Slo + gi, sz);
        }
    };
    issueA(0);
    asm volatile("cp.async.commit_group;" ::: "memory");

    float acc[2][8][4];
#pragma unroll
    for (int a = 0; a < 2; a++)
#pragma unroll
        for (int b = 0; b < 8; b++)
#pragma unroll
            for (int c = 0; c < 4; c++) acc[a][b][c] = 0.f;

    int krow = lane & 15;
    int kof  = (lane >> 4) * 8;

    for (int kc = 0; kc < 4; kc++) {
        if (kc < 3) {
            issueA(kc + 1);
            asm volatile("cp.async.commit_group;" ::: "memory");
            asm volatile("cp.async.wait_group 1;" ::: "memory");
        } else {
            asm volatile("cp.async.wait_group 0;" ::: "memory");
        }
        __syncthreads();

        uint32_t ahb = sb + SM_A0 + (kc & 1) * 2 * ASZ;
        uint32_t alb = ahb + ASZ;
#pragma unroll
        for (int kk = 0; kk < 4; kk++) {
            uint32_t ahi[2][4], alo[2][4], bhi[4][4], blo[4][4];
            uint32_t a_off = (wm * 32 + krow) * (A_STRIDE * 2) + (kk * 16 + kof) * 2;
            ldsm4(ahi[0], ahb + a_off);
            ldsm4(ahi[1], ahb + a_off + 16 * (A_STRIDE * 2));
            ldsm4(alo[0], alb + a_off);
            ldsm4(alo[1], alb + a_off + 16 * (A_STRIDE * 2));
            int kg = kc * 64 + kk * 16 + kof;
#pragma unroll
            for (int nq = 0; nq < 4; nq++) {
                uint32_t b_off = (wn * 64 + nq * 16 + krow) * (B_STRIDE * 2) + kg * 2;
                ldsm4(bhi[nq], sb + SM_B_HI + b_off);
                ldsm4(blo[nq], sb + SM_B_LO + b_off);
            }
#pragma unroll
            for (int mt = 0; mt < 2; mt++) {
#pragma unroll
                for (int nq = 0; nq < 4; nq++) {
                    float* cl = acc[mt][nq * 2];
                    float* ch = acc[mt][nq * 2 + 1];
                    // hi*hi
                    mma16816(cl, ahi[mt], bhi[nq][0], bhi[nq][2]);
                    mma16816(ch, ahi[mt], bhi[nq][1], bhi[nq][3]);
                    // hi*lo
                    mma16816(cl, ahi[mt], blo[nq][0], blo[nq][2]);
                    mma16816(ch, ahi[mt], blo[nq][1], blo[nq][3]);
                    // lo*hi
                    mma16816(cl, alo[mt], bhi[nq][0], bhi[nq][2]);
                    mma16816(ch, alo[mt], bhi[nq][1], bhi[nq][3]);
                }
            }
        }
        __syncthreads();
    }

    // ---- epilogue: ReLU + store fp32 ---------------------------------------
    int gm_base = m0 + wm * 32 + (lane >> 2);
    int gn_base = n0 + wn * 64 + (lane & 3) * 2;
#pragma unroll
    for (int mt = 0; mt < 2; mt++) {
#pragma unroll
        for (int nn = 0; nn < 8; nn++) {
            float* c = acc[mt][nn];
            int gm = gm_base + mt * 16;
            int gn = gn_base + nn * 8;
            if (gm < Nn) {
                float2 v = make_float2(fmaxf(c[0], 0.f), fmaxf(c[1], 0.f));
                *(float2*)(g_H + ((size_t)r * Nn + gm) * Hh + gn) = v;
            }
            if (gm + 8 < Nn) {
                float2 v = make_float2(fmaxf(c[2], 0.f), fmaxf(c[3], 0.f));
                *(float2*)(g_H + ((size_t)r * Nn + gm + 8) * Hh + gn) = v;
            }
        }
    }
}

// ---------------- layer-1 mean ----------------------------------------------
__global__ void k_mean() {
    int idx = blockIdx.x * blockDim.x + threadIdx.x;
    const int total = Nn * Hh / 4;
    if (idx >= total) return;
    const float4* h = (const float4*)g_H;
    size_t off = (size_t)Nn * Hh / 4;
    float4 a = h[idx], b = h[idx + off], c = h[idx + 2 * off], d = h[idx + 3 * off];
    float4 m;
    m.x = 0.25f * (a.x + b.x + c.x + d.x);
    m.y = 0.25f * (a.y + b.y + c.y + d.y);
    m.z = 0.25f * (a.z + b.z + c.z + d.z);
    m.w = 0.25f * (a.w + b.w + c.w + d.w);
    ((float4*)g_h1)[idx] = m;
}

// ---------------- attention + residual fusion + output GEMM -----------------
__global__ __launch_bounds__(256) void k_attn(const float* __restrict__ att_q,
                                              const float* __restrict__ tau_p,
                                              const float* __restrict__ W_out,
                                              const float* __restrict__ b_out,
                                              float* __restrict__ out) {
    int n = blockIdx.x * 8 + (threadIdx.x >> 5);
    if (n >= Nn) return;
    int lane = threadIdx.x & 31;

    float q[8];
#pragma unroll
    for (int k = 0; k < 8; k++) q[k] = att_q[lane + 32 * k];

    float v[4][8];
    float sc[4];
#pragma unroll
    for (int r = 0; r < 4; r++) {
        const float* h = g_H + ((size_t)r * Nn + n) * Hh;
        float s = 0.f;
#pragma unroll
        for (int k = 0; k < 8; k++) {
            v[r][k] = h[lane + 32 * k];
            s += v[r][k] * q[k];
        }
#pragma unroll
        for (int o = 16; o; o >>= 1) s += __shfl_xor_sync(0xffffffffu, s, o);
        sc[r] = s;
    }
    float tc = fminf(fmaxf(tau_p[0], 0.5f), 5.0f);
    float inv = 1.0f / tc;
    float s0 = sc[0] * inv, s1 = sc[1] * inv, s2 = sc[2] * inv, s3 = sc[3] * inv;
    float m = fmaxf(fmaxf(s0, s1), fmaxf(s2, s3));
    float e0 = expf(s0 - m), e1 = expf(s1 - m), e2 = expf(s2 - m), e3 = expf(s3 - m);
    float se = e0 + e1 + e2 + e3;
    float al[4] = {e0 / se, e1 / se, e2 / se, e3 / se};

    float h2[8];
#pragma unroll
    for (int k = 0; k < 8; k++)
        h2[k] = (0.25f + al[0]) * v[0][k] + (0.25f + al[1]) * v[1][k] +
                (0.25f + al[2]) * v[2][k] + (0.25f + al[3]) * v[3][k];

    float acc[16];
#pragma unroll
    for (int c = 0; c < 16; c++) acc[c] = 0.f;
#pragma unroll
    for (int k = 0; k < 8; k++) {
        int idx = lane + 32 * k;
        const float4* wr = (const float4*)(W_out + (size_t)idx * 16);
        float4 w0 = wr[0], w1 = wr[1], w2 = wr[2], w3 = wr[3];
        float hv = h2[k];
        acc[0]  += hv * w0.x; acc[1]  += hv * w0.y; acc[2]  += hv * w0.z; acc[3]  += hv * w0.w;
        acc[4]  += hv * w1.x; acc[5]  += hv * w1.y; acc[6]  += hv * w1.z; acc[7]  += hv * w1.w;
        acc[8]  += hv * w2.x; acc[9]  += hv * w2.y; acc[10] += hv * w2.z; acc[11] += hv * w2.w;
        acc[12] += hv * w3.x; acc[13] += hv * w3.y; acc[14] += hv * w3.z; acc[15] += hv * w3.w;
    }
#pragma unroll
    for (int c = 0; c < 16; c++)
#pragma unroll
        for (int o = 16; o; o >>= 1) acc[c] += __shfl_xor_sync(0xffffffffu, acc[c], o);

    if (lane < 16) {
        float lg = 0.f;
#pragma unroll
        for (int c = 0; c < 16; c++)
            if (lane == c) lg = acc[c];
        out[(size_t)n * Cc + lane] = lg + b_out[lane];
    }
    if (lane < 4) {
        float a = al[0];
        if (lane == 1) a = al[1];
        if (lane == 2) a = al[2];
        if (lane == 3) a = al[3];
        out[(size_t)Nn * Cc + (size_t)n * Rr + lane] = a;
    }
}

// ---------------- launch ----------------------------------------------------
extern "C" void kernel_launch(void* const* d_in, const int* in_sizes, int n_in,
                              void* d_out, int out_size) {
    const float* X     = (const float*)d_in[0];
    const int*   EI    = (const int*)d_in[1];
    const float* W1    = (const float*)d_in[2];
    const float* W2    = (const float*)d_in[3];
    const float* att_q = (const float*)d_in[4];
    const float* tau   = (const float*)d_in[5];
    const float* W_out = (const float*)d_in[6];
    const float* b_out = (const float*)d_in[7];
    float* out = (float*)d_out;
    (void)in_sizes; (void)n_in; (void)out_size;

    cudaFuncSetAttribute(k_gemm_mma, cudaFuncAttributeMaxDynamicSharedMemorySize, SMEM_GEMM);

    // CSR build
    k_zero_deg<<<(Rr * Nn + 255) / 256, 256>>>();
    k_hist<<<(Rr * Ee + 255) / 256, 256>>>(EI);
    k_dinv<<<(Rr * Nn + 255) / 256, 256>>>();
    k_scan<<<Rr, 1024>>>();
    k_scatter<<<(Rr * Ee + 255) / 256, 256>>>(EI);

    dim3 spmm_grid((Nn + 7) / 8, Rr);
    dim3 gemm_grid((Nn + 127) / 128, Hh / 128, Rr);

    // Layer 1
    k_spmm<<<spmm_grid, 256>>>(X, 0);
    k_splitW<<<(Rr * 256 * 256 + 255) / 256, 256>>>(W1);
    k_gemm_mma<<<gemm_grid, 256, SMEM_GEMM>>>();
    k_mean<<<(Nn * Hh / 4 + 255) / 256, 256>>>();

    // Layer 2
    k_spmm<<<spmm_grid, 256>>>(X, 1);
    k_splitW<<<(Rr * 256 * 256 + 255) / 256, 256>>>(W2);
    k_gemm_mma<<<gemm_grid, 256, SMEM_GEMM>>>();

    // Attention + output head
    k_attn<<<(Nn + 7) / 8, 256>>>(att_q, tau, W_out, b_out, out);
}

// round 5
// speedup vs baseline: 1.6898x; 1.1362x over previous
#include <cuda_runtime.h>
#include <cuda_bf16.h>
#include <cuda_fp16.h>
#include <cstdint>
#include <math.h>

#define Nn 50000
#define Rr 4
#define Ee 1600000
#define Hh 256
#define Cc 16
#define NBLK 13   // ceil(50000 / 4096)

// ---------------- scratch (device globals; no runtime allocation) ----------
__device__ int   g_deg_r[Rr * Nn];
__device__ int   g_deg_c[Rr * Nn];
__device__ float g_dinv_r[Rr * Nn];
__device__ float g_dinv_c[Rr * Nn];
__device__ int   g_row_ptr[Rr * (Nn + 1)];
__device__ int   g_cursor[Rr * Nn];
__device__ int   g_blksum[Rr * NBLK];
__device__ int   g_cols[Rr * Ee];
__device__ float g_wgt[Rr * Ee];
// fp16 gather sources
__device__ __half g_Xh[(size_t)Nn * Hh];
__device__ __half g_h1h[(size_t)Nn * Hh];
// bf16 hi/lo split of SpMM outputs: [R][N][256] bf16, 32 uint4 per row
__device__ uint4 g_Shi[(size_t)Rr * Nn * 32];
__device__ uint4 g_Slo[(size_t)Rr * Nn * 32];
// bf16 hi/lo split of W transposed to n-major: [R][n=256][k=256]
__device__ uint4 g_Bhi[Rr * 256 * 32];
__device__ uint4 g_Blo[Rr * 256 * 32];
__device__ float g_H[(size_t)Rr * Nn * Hh];

// ---------------- low-level helpers (all base-arch PTX) ---------------------
__device__ __forceinline__ uint32_t smem_to_u32(const void* p) {
    uint32_t a;
    asm("{ .reg .u64 t; cvta.to.shared.u64 t, %1; cvt.u32.u64 %0, t; }" : "=r"(a) : "l"(p));
    return a;
}
__device__ __forceinline__ void cp16(uint32_t dst, const void* src, int sz) {
    asm volatile("cp.async.cg.shared.global [%0], [%1], 16, %2;"
                 :: "r"(dst), "l"(src), "r"(sz));
}
__device__ __forceinline__ void ldsm4(uint32_t* r, uint32_t addr) {
    asm volatile("ldmatrix.sync.aligned.m8n8.x4.shared.b16 {%0,%1,%2,%3}, [%4];"
                 : "=r"(r[0]), "=r"(r[1]), "=r"(r[2]), "=r"(r[3]) : "r"(addr));
}
__device__ __forceinline__ void mma16816(float* c, const uint32_t* a, uint32_t b0, uint32_t b1) {
    asm volatile("mma.sync.aligned.m16n8k16.row.col.f32.bf16.bf16.f32 "
                 "{%0,%1,%2,%3}, {%4,%5,%6,%7}, {%8,%9}, {%0,%1,%2,%3};"
                 : "+f"(c[0]), "+f"(c[1]), "+f"(c[2]), "+f"(c[3])
                 : "r"(a[0]), "r"(a[1]), "r"(a[2]), "r"(a[3]), "r"(b0), "r"(b1));
}

// ---------------- bf16 split helpers ----------------------------------------
__device__ __forceinline__ void split2(float x, unsigned short& h, unsigned short& l) {
    __nv_bfloat16 hb = __float2bfloat16(x);
    h = __bfloat16_as_ushort(hb);
    l = __bfloat16_as_ushort(__float2bfloat16(x - __bfloat162float(hb)));
}
__device__ __forceinline__ void split_store4(uint2* hp, uint2* lp, float4 v) {
    unsigned short h0, h1, h2, h3, l0, l1, l2, l3;
    split2(v.x, h0, l0); split2(v.y, h1, l1); split2(v.z, h2, l2); split2(v.w, h3, l3);
    uint2 hv, lv;
    hv.x = (uint32_t)h0 | ((uint32_t)h1 << 16); hv.y = (uint32_t)h2 | ((uint32_t)h3 << 16);
    lv.x = (uint32_t)l0 | ((uint32_t)l1 << 16); lv.y = (uint32_t)l2 | ((uint32_t)l3 << 16);
    *hp = hv; *lp = lv;
}

// ---------------- CSR construction ------------------------------------------
__global__ void k_zero_deg() {
    int i = blockIdx.x * blockDim.x + threadIdx.x;
    if (i < Rr * Nn) { g_deg_r[i] = 0; g_deg_c[i] = 0; }
}
__global__ void k_hist(const int* __restrict__ ei) {
    int idx = blockIdx.x * blockDim.x + threadIdx.x;
    if (idx >= Rr * Ee) return;
    int r = idx / Ee, e = idx - r * Ee;
    const int* base = ei + (size_t)r * 2 * Ee;
    atomicAdd(&g_deg_r[r * Nn + base[e]], 1);
    atomicAdd(&g_deg_c[r * Nn + base[Ee + e]], 1);
}
__global__ void k_dinv() {
    int i = blockIdx.x * blockDim.x + threadIdx.x;
    if (i >= Rr * Nn) return;
    g_dinv_r[i] = rsqrtf(fmaxf((float)g_deg_r[i], 1.0f));
    g_dinv_c[i] = rsqrtf(fmaxf((float)g_deg_c[i], 1.0f));
}

// ---- multi-block scan: phase 1 (local exclusive scan + block totals) -------
__global__ __launch_bounds__(1024) void k_scan1() {
    int r = blockIdx.y, b = blockIdx.x;
    int t = threadIdx.x, lane = t & 31, w = t >> 5;
    __shared__ int wsum[32];
    int i0 = b * 4096 + t * 4;
    int v[4], s = 0;
#pragma unroll
    for (int j = 0; j < 4; j++) {
        v[j] = (i0 + j < Nn) ? g_deg_r[r * Nn + i0 + j] : 0;
        s += v[j];
    }
    int x = s;
#pragma unroll
    for (int o = 1; o < 32; o <<= 1) {
        int y = __shfl_up_sync(0xffffffffu, x, o);
        if (lane >= o) x += y;
    }
    if (lane == 31) wsum[w] = x;
    __syncthreads();
    if (w == 0) {
        int s2 = wsum[lane];
#pragma unroll
        for (int o = 1; o < 32; o <<= 1) {
            int y = __shfl_up_sync(0xffffffffu, s2, o);
            if (lane >= o) s2 += y;
        }
        wsum[lane] = s2;
    }
    __syncthreads();
    int woff = (w == 0) ? 0 : wsum[w - 1];
    int run = woff + x - s;   // exclusive prefix within block
#pragma unroll
    for (int j = 0; j < 4; j++) {
        if (i0 + j < Nn) g_row_ptr[r * (Nn + 1) + i0 + j] = run;
        run += v[j];
    }
    if (t == 1023) g_blksum[r * NBLK + b] = woff + x;
}
// ---- phase 2: scan per-relation block totals (tiny) -------------------------
__global__ void k_scan2() {
    int t = threadIdx.x, lane = t & 31, w = t >> 5;   // 128 threads, w = relation
    int v = (lane < NBLK) ? g_blksum[w * NBLK + lane] : 0;
    int x = v;
#pragma unroll
    for (int o = 1; o < 32; o <<= 1) {
        int y = __shfl_up_sync(0xffffffffu, x, o);
        if (lane >= o) x += y;
    }
    if (lane < NBLK) g_blksum[w * NBLK + lane] = x - v;
    if (lane == NBLK - 1) g_row_ptr[w * (Nn + 1) + Nn] = x;
}
// ---- phase 3: add block offsets, init cursors -------------------------------
__global__ __launch_bounds__(1024) void k_scan3() {
    int r = blockIdx.y, b = blockIdx.x;
    int off = g_blksum[r * NBLK + b];
    int i0 = b * 4096 + threadIdx.x * 4;
#pragma unroll
    for (int j = 0; j < 4; j++) {
        int i = i0 + j;
        if (i < Nn) {
            int p = g_row_ptr[r * (Nn + 1) + i] + off;
            g_row_ptr[r * (Nn + 1) + i] = p;
            g_cursor[r * Nn + i] = p;
        }
    }
}

__global__ void k_scatter(const int* __restrict__ ei) {
    int idx = blockIdx.x * blockDim.x + threadIdx.x;
    if (idx >= Rr * Ee) return;
    int r = idx / Ee, e = idx - r * Ee;
    const int* base = ei + (size_t)r * 2 * Ee;
    int row = base[e];
    int col = base[Ee + e];
    int pos = atomicAdd(&g_cursor[r * Nn + row], 1);
    size_t o = (size_t)r * Ee + pos;
    g_cols[o] = col;
    g_wgt[o] = g_dinv_r[r * Nn + row] * g_dinv_c[r * Nn + col];
}

// ---------------- fp32 -> fp16 conversion ------------------------------------
__global__ void k_cvt(const float* __restrict__ x, __half* __restrict__ dst) {
    int idx = blockIdx.x * blockDim.x + threadIdx.x;
    const int total = Nn * Hh / 4;
    if (idx >= total) return;
    float4 v = ((const float4*)x)[idx];
    __half2 p0 = __floats2half2_rn(v.x, v.y);
    __half2 p1 = __floats2half2_rn(v.z, v.w);
    uint2 u;
    u.x = *(const uint32_t*)&p0;
    u.y = *(const uint32_t*)&p1;
    ((uint2*)dst)[idx] = u;
}

// ---------------- SpMM: warp per row, fp16 gather, bf16 hi/lo output --------
__global__ __launch_bounds__(256) void k_spmm(int use_h1) {
    int r = blockIdx.y;
    int n = blockIdx.x * 8 + (threadIdx.x >> 5);
    if (n >= Nn) return;
    int lane = threadIdx.x & 31;
    const uint4* src = (const uint4*)(use_h1 ? g_h1h : g_Xh);   // row = 32 uint4
    int beg = g_row_ptr[r * (Nn + 1) + n];
    int end = g_row_ptr[r * (Nn + 1) + n + 1];
    const int*   cols = g_cols + (size_t)r * Ee;
    const float* ws   = g_wgt  + (size_t)r * Ee;
    float acc[8];
#pragma unroll
    for (int j = 0; j < 8; j++) acc[j] = 0.f;
    for (int e = beg; e < end; ++e) {
        int c = cols[e];
        float w = ws[e];
        uint4 v = src[(size_t)c * 32 + lane];
        const __half2* h = (const __half2*)&v;
        float2 f;
        f = __half22float2(h[0]); acc[0] += w * f.x; acc[1] += w * f.y;
        f = __half22float2(h[1]); acc[2] += w * f.x; acc[3] += w * f.y;
        f = __half22float2(h[2]); acc[4] += w * f.x; acc[5] += w * f.y;
        f = __half22float2(h[3]); acc[6] += w * f.x; acc[7] += w * f.y;
    }
    size_t rb = ((size_t)r * Nn + n) * 64;
    split_store4((uint2*)g_Shi + rb + 2 * lane,     (uint2*)g_Slo + rb + 2 * lane,
                 make_float4(acc[0], acc[1], acc[2], acc[3]));
    split_store4((uint2*)g_Shi + rb + 2 * lane + 1, (uint2*)g_Slo + rb + 2 * lane + 1,
                 make_float4(acc[4], acc[5], acc[6], acc[7]));
}

// ---------------- W split+transpose: Bhi[r][n][k] = bf16split(W[r][k][n]) ---
__global__ void k_splitW(const float* __restrict__ W) {
    int idx = blockIdx.x * blockDim.x + threadIdx.x;
    if (idx >= Rr * 256 * 256) return;
    int r = idx >> 16;
    int n = (idx >> 8) & 255;
    int k = idx & 255;
    float w = W[((size_t)r << 16) + ((size_t)k << 8) + n];
    unsigned short h, l;
    split2(w, h, l);
    size_t o = ((size_t)r << 16) + ((size_t)n << 8) + k;
    ((unsigned short*)g_Bhi)[o] = h;
    ((unsigned short*)g_Blo)[o] = l;
}

// ---------------- mma.sync GEMM: H[r] = ReLU(S[r] @ W[r]) -------------------
#define A_STRIDE 72
#define B_STRIDE 264
#define ASZ (128 * A_STRIDE * 2)
#define SM_B_HI 0
#define SM_B_LO (128 * B_STRIDE * 2)
#define SM_A0   (2 * 128 * B_STRIDE * 2)
#define SMEM_GEMM (SM_A0 + 4 * ASZ)

__global__ __launch_bounds__(256) void k_gemm_mma() {
    extern __shared__ char smem[];
    uint32_t sb = smem_to_u32(smem);
    int tid = threadIdx.x, lane = tid & 31, wid = tid >> 5;
    int wm = wid >> 1, wn = wid & 1;
    int r = blockIdx.z, m0 = blockIdx.x * 128, n0 = blockIdx.y * 128;

    {
        const uint4* bh = g_Bhi + ((size_t)(r * 256 + n0)) * 32;
        const uint4* bl = g_Blo + ((size_t)(r * 256 + n0)) * 32;
#pragma unroll
        for (int j = 0; j < 16; j++) {
            int lin = tid + j * 256;
            int row = lin >> 5, ch = lin & 31;
            uint32_t so = row * (B_STRIDE * 2) + ch * 16;
            cp16(sb + SM_B_HI + so, bh + row * 32 + ch, 16);
            cp16(sb + SM_B_LO + so, bl + row * 32 + ch, 16);
        }
    }
    asm volatile("cp.async.commit_group;" ::: "memory");

    auto issueA = [&](int kc) {
        int s = kc & 1;
        uint32_t abase = sb + SM_A0 + s * 2 * ASZ;
#pragma unroll
        for (int j = 0; j < 4; j++) {
            int lin = tid + j * 256;
            int row = lin >> 3, ch = lin & 7;
            int gm = m0 + row;
            int sz = (gm < Nn) ? 16 : 0;
            int gmc = (gm < Nn) ? gm : (Nn - 1);
            size_t gi = ((size_t)r * Nn + gmc) * 32 + kc * 8 + ch;
            uint32_t so = row * (A_STRIDE * 2) + ch * 16;
            cp16(abase + so, g_Shi + gi, sz);
            cp16(abase + ASZ + so, g_Slo + gi, sz);
        }
    };
    issueA(0);
    asm volatile("cp.async.commit_group;" ::: "memory");

    float acc[2][8][4];
#pragma unroll
    for (int a = 0; a < 2; a++)
#pragma unroll
        for (int b = 0; b < 8; b++)
#pragma unroll
            for (int c = 0; c < 4; c++) acc[a][b][c] = 0.f;

    int krow = lane & 15;
    int kof  = (lane >> 4) * 8;

    for (int kc = 0; kc < 4; kc++) {
        if (kc < 3) {
            issueA(kc + 1);
            asm volatile("cp.async.commit_group;" ::: "memory");
            asm volatile("cp.async.wait_group 1;" ::: "memory");
        } else {
            asm volatile("cp.async.wait_group 0;" ::: "memory");
        }
        __syncthreads();

        uint32_t ahb = sb + SM_A0 + (kc & 1) * 2 * ASZ;
        uint32_t alb = ahb + ASZ;
#pragma unroll
        for (int kk = 0; kk < 4; kk++) {
            uint32_t ahi[2][4], alo[2][4], bhi[4][4], blo[4][4];
            uint32_t a_off = (wm * 32 + krow) * (A_STRIDE * 2) + (kk * 16 + kof) * 2;
            ldsm4(ahi[0], ahb + a_off);
            ldsm4(ahi[1], ahb + a_off + 16 * (A_STRIDE * 2));
            ldsm4(alo[0], alb + a_off);
            ldsm4(alo[1], alb + a_off + 16 * (A_STRIDE * 2));
            int kg = kc * 64 + kk * 16 + kof;
#pragma unroll
            for (int nq = 0; nq < 4; nq++) {
                uint32_t b_off = (wn * 64 + nq * 16 + krow) * (B_STRIDE * 2) + kg * 2;
                ldsm4(bhi[nq], sb + SM_B_HI + b_off);
                ldsm4(blo[nq], sb + SM_B_LO + b_off);
            }
#pragma unroll
            for (int mt = 0; mt < 2; mt++) {
#pragma unroll
                for (int nq = 0; nq < 4; nq++) {
                    float* cl = acc[mt][nq * 2];
                    float* ch = acc[mt][nq * 2 + 1];
                    mma16816(cl, ahi[mt], bhi[nq][0], bhi[nq][2]);
                    mma16816(ch, ahi[mt], bhi[nq][1], bhi[nq][3]);
                    mma16816(cl, ahi[mt], blo[nq][0], blo[nq][2]);
                    mma16816(ch, ahi[mt], blo[nq][1], blo[nq][3]);
                    mma16816(cl, alo[mt], bhi[nq][0], bhi[nq][2]);
                    mma16816(ch, alo[mt], bhi[nq][1], bhi[nq][3]);
                }
            }
        }
        __syncthreads();
    }

    int gm_base = m0 + wm * 32 + (lane >> 2);
    int gn_base = n0 + wn * 64 + (lane & 3) * 2;
#pragma unroll
    for (int mt = 0; mt < 2; mt++) {
#pragma unroll
        for (int nn = 0; nn < 8; nn++) {
            float* c = acc[mt][nn];
            int gm = gm_base + mt * 16;
            int gn = gn_base + nn * 8;
            if (gm < Nn) {
                float2 v = make_float2(fmaxf(c[0], 0.f), fmaxf(c[1], 0.f));
                *(float2*)(g_H + ((size_t)r * Nn + gm) * Hh + gn) = v;
            }
            if (gm + 8 < Nn) {
                float2 v = make_float2(fmaxf(c[2], 0.f), fmaxf(c[3], 0.f));
                *(float2*)(g_H + ((size_t)r * Nn + gm + 8) * Hh + gn) = v;
            }
        }
    }
}

// ---------------- layer-1 mean -> fp16 h1 -----------------------------------
__global__ void k_mean() {
    int idx = blockIdx.x * blockDim.x + threadIdx.x;
    const int total = Nn * Hh / 4;
    if (idx >= total) return;
    const float4* h = (const float4*)g_H;
    size_t off = (size_t)Nn * Hh / 4;
    float4 a = h[idx], b = h[idx + off], c = h[idx + 2 * off], d = h[idx + 3 * off];
    float4 m;
    m.x = 0.25f * (a.x + b.x + c.x + d.x);
    m.y = 0.25f * (a.y + b.y + c.y + d.y);
    m.z = 0.25f * (a.z + b.z + c.z + d.z);
    m.w = 0.25f * (a.w + b.w + c.w + d.w);
    __half2 p0 = __floats2half2_rn(m.x, m.y);
    __half2 p1 = __floats2half2_rn(m.z, m.w);
    uint2 u;
    u.x = *(const uint32_t*)&p0;
    u.y = *(const uint32_t*)&p1;
    ((uint2*)g_h1h)[idx] = u;
}

// ---------------- attention + residual fusion + output GEMM -----------------
__global__ __launch_bounds__(256) void k_attn(const float* __restrict__ att_q,
                                              const float* __restrict__ tau_p,
                                              const float* __restrict__ W_out,
                                              const float* __restrict__ b_out,
                                              float* __restrict__ out) {
    int n = blockIdx.x * 8 + (threadIdx.x >> 5);
    if (n >= Nn) return;
    int lane = threadIdx.x & 31;

    float q[8];
#pragma unroll
    for (int k = 0; k < 8; k++) q[k] = att_q[lane + 32 * k];

    float v[4][8];
    float sc[4];
#pragma unroll
    for (int r = 0; r < 4; r++) {
        const float* h = g_H + ((size_t)r * Nn + n) * Hh;
        float s = 0.f;
#pragma unroll
        for (int k = 0; k < 8; k++) {
            v[r][k] = h[lane + 32 * k];
            s += v[r][k] * q[k];
        }
#pragma unroll
        for (int o = 16; o; o >>= 1) s += __shfl_xor_sync(0xffffffffu, s, o);
        sc[r] = s;
    }
    float tc = fminf(fmaxf(tau_p[0], 0.5f), 5.0f);
    float inv = 1.0f / tc;
    float s0 = sc[0] * inv, s1 = sc[1] * inv, s2 = sc[2] * inv, s3 = sc[3] * inv;
    float m = fmaxf(fmaxf(s0, s1), fmaxf(s2, s3));
    float e0 = expf(s0 - m), e1 = expf(s1 - m), e2 = expf(s2 - m), e3 = expf(s3 - m);
    float se = e0 + e1 + e2 + e3;
    float al[4] = {e0 / se, e1 / se, e2 / se, e3 / se};

    float h2[8];
#pragma unroll
    for (int k = 0; k < 8; k++)
        h2[k] = (0.25f + al[0]) * v[0][k] + (0.25f + al[1]) * v[1][k] +
                (0.25f + al[2]) * v[2][k] + (0.25f + al[3]) * v[3][k];

    float acc[16];
#pragma unroll
    for (int c = 0; c < 16; c++) acc[c] = 0.f;
#pragma unroll
    for (int k = 0; k < 8; k++) {
        int idx = lane + 32 * k;
        const float4* wr = (const float4*)(W_out + (size_t)idx * 16);
        float4 w0 = wr[0], w1 = wr[1], w2 = wr[2], w3 = wr[3];
        float hv = h2[k];
        acc[0]  += hv * w0.x; acc[1]  += hv * w0.y; acc[2]  += hv * w0.z; acc[3]  += hv * w0.w;
        acc[4]  += hv * w1.x; acc[5]  += hv * w1.y; acc[6]  += hv * w1.z; acc[7]  += hv * w1.w;
        acc[8]  += hv * w2.x; acc[9]  += hv * w2.y; acc[10] += hv * w2.z; acc[11] += hv * w2.w;
        acc[12] += hv * w3.x; acc[13] += hv * w3.y; acc[14] += hv * w3.z; acc[15] += hv * w3.w;
    }
#pragma unroll
    for (int c = 0; c < 16; c++)
#pragma unroll
        for (int o = 16; o; o >>= 1) acc[c] += __shfl_xor_sync(0xffffffffu, acc[c], o);

    if (lane < 16) {
        float lg = 0.f;
#pragma unroll
        for (int c = 0; c < 16; c++)
            if (lane == c) lg = acc[c];
        out[(size_t)n * Cc + lane] = lg + b_out[lane];
    }
    if (lane < 4) {
        float a = al[0];
        if (lane == 1) a = al[1];
        if (lane == 2) a = al[2];
        if (lane == 3) a = al[3];
        out[(size_t)Nn * Cc + (size_t)n * Rr + lane] = a;
    }
}

// ---------------- launch ----------------------------------------------------
extern "C" void kernel_launch(void* const* d_in, const int* in_sizes, int n_in,
                              void* d_out, int out_size) {
    const float* X     = (const float*)d_in[0];
    const int*   EI    = (const int*)d_in[1];
    const float* W1    = (const float*)d_in[2];
    const float* W2    = (const float*)d_in[3];
    const float* att_q = (const float*)d_in[4];
    const float* tau   = (const float*)d_in[5];
    const float* W_out = (const float*)d_in[6];
    const float* b_out = (const float*)d_in[7];
    float* out = (float*)d_out;
    (void)in_sizes; (void)n_in; (void)out_size;

    cudaFuncSetAttribute(k_gemm_mma, cudaFuncAttributeMaxDynamicSharedMemorySize, SMEM_GEMM);

    // CSR build
    k_zero_deg<<<(Rr * Nn + 255) / 256, 256>>>();
    k_hist<<<(Rr * Ee + 255) / 256, 256>>>(EI);
    k_dinv<<<(Rr * Nn + 255) / 256, 256>>>();
    k_scan1<<<dim3(NBLK, Rr), 1024>>>();
    k_scan2<<<1, 128>>>();
    k_scan3<<<dim3(NBLK, Rr), 1024>>>();
    k_scatter<<<(Rr * Ee + 255) / 256, 256>>>(EI);

    // fp16 copy of X for gathers
    __half* xh;
    cudaGetSymbolAddress((void**)&xh, g_Xh);
    k_cvt<<<(Nn * Hh / 4 + 255) / 256, 256>>>(X, xh);

    dim3 spmm_grid((Nn + 7) / 8, Rr);
    dim3 gemm_grid((Nn + 127) / 128, Hh / 128, Rr);

    // Layer 1
    k_spmm<<<spmm_grid, 256>>>(0);
    k_splitW<<<(Rr * 256 * 256 + 255) / 256, 256>>>(W1);
    k_gemm_mma<<<gemm_grid, 256, SMEM_GEMM>>>();
    k_mean<<<(Nn * Hh / 4 + 255) / 256, 256>>>();

    // Layer 2
    k_spmm<<<spmm_grid, 256>>>(1);
    k_splitW<<<(Rr * 256 * 256 + 255) / 256, 256>>>(W2);
    k_gemm_mma<<<gemm_grid, 256, SMEM_GEMM>>>();

    // Attention + output head
    k_attn<<<(Nn + 7) / 8, 256>>>(att_q, tau, W_out, b_out, out);
}

// round 6
// speedup vs baseline: 1.8216x; 1.0780x over previous
#include <cuda_runtime.h>
#include <cuda_bf16.h>
#include <cuda_fp16.h>
#include <cstdint>
#include <math.h>

#define Nn 50000
#define Rr 4
#define Ee 1600000
#define Hh 256
#define Cc 16
#define NBLK 13   // ceil(50000 / 4096)

// ---------------- scratch (device globals; no runtime allocation) ----------
__device__ int   g_deg_r[Rr * Nn];
__device__ int   g_deg_c[Rr * Nn];
__device__ float g_dinv_r[Rr * Nn];
__device__ float g_dinv_c[Rr * Nn];
__device__ int   g_row_ptr[Rr * (Nn + 1)];
__device__ int   g_cursor[Rr * Nn];
__device__ int   g_blksum[Rr * NBLK];
__device__ int2  g_edge[(size_t)Rr * Ee];   // packed {col, wgt_bits}
// fp16 gather sources
__device__ __half g_Xh[(size_t)Nn * Hh];
__device__ __half g_h1h[(size_t)Nn * Hh];
// bf16 hi/lo split of SpMM outputs: [R][N][256] bf16, 32 uint4 per row
__device__ uint4 g_Shi[(size_t)Rr * Nn * 32];
__device__ uint4 g_Slo[(size_t)Rr * Nn * 32];
// bf16 hi/lo split of W transposed to n-major: [R][n=256][k=256]
__device__ uint4 g_Bhi[Rr * 256 * 32];
__device__ uint4 g_Blo[Rr * 256 * 32];
__device__ float g_H[(size_t)Rr * Nn * Hh];

// ---------------- low-level helpers (all base-arch PTX) ---------------------
__device__ __forceinline__ uint32_t smem_to_u32(const void* p) {
    uint32_t a;
    asm("{ .reg .u64 t; cvta.to.shared.u64 t, %1; cvt.u32.u64 %0, t; }" : "=r"(a) : "l"(p));
    return a;
}
__device__ __forceinline__ void cp16(uint32_t dst, const void* src, int sz) {
    asm volatile("cp.async.cg.shared.global [%0], [%1], 16, %2;"
                 :: "r"(dst), "l"(src), "r"(sz));
}
__device__ __forceinline__ void ldsm4(uint32_t* r, uint32_t addr) {
    asm volatile("ldmatrix.sync.aligned.m8n8.x4.shared.b16 {%0,%1,%2,%3}, [%4];"
                 : "=r"(r[0]), "=r"(r[1]), "=r"(r[2]), "=r"(r[3]) : "r"(addr));
}
__device__ __forceinline__ void mma16816(float* c, const uint32_t* a, uint32_t b0, uint32_t b1) {
    asm volatile("mma.sync.aligned.m16n8k16.row.col.f32.bf16.bf16.f32 "
                 "{%0,%1,%2,%3}, {%4,%5,%6,%7}, {%8,%9}, {%0,%1,%2,%3};"
                 : "+f"(c[0]), "+f"(c[1]), "+f"(c[2]), "+f"(c[3])
                 : "r"(a[0]), "r"(a[1]), "r"(a[2]), "r"(a[3]), "r"(b0), "r"(b1));
}

// ---------------- bf16 split helpers ----------------------------------------
__device__ __forceinline__ void split2(float x, unsigned short& h, unsigned short& l) {
    __nv_bfloat16 hb = __float2bfloat16(x);
    h = __bfloat16_as_ushort(hb);
    l = __bfloat16_as_ushort(__float2bfloat16(x - __bfloat162float(hb)));
}
__device__ __forceinline__ void split_store4(uint2* hp, uint2* lp, float4 v) {
    unsigned short h0, h1, h2, h3, l0, l1, l2, l3;
    split2(v.x, h0, l0); split2(v.y, h1, l1); split2(v.z, h2, l2); split2(v.w, h3, l3);
    uint2 hv, lv;
    hv.x = (uint32_t)h0 | ((uint32_t)h1 << 16); hv.y = (uint32_t)h2 | ((uint32_t)h3 << 16);
    lv.x = (uint32_t)l0 | ((uint32_t)l1 << 16); lv.y = (uint32_t)l2 | ((uint32_t)l3 << 16);
    *hp = hv; *lp = lv;
}

// ---------------- CSR construction ------------------------------------------
__global__ void k_zero_deg() {
    int i = blockIdx.x * blockDim.x + threadIdx.x;
    if (i < Rr * Nn) { g_deg_r[i] = 0; g_deg_c[i] = 0; }
}
__global__ void k_hist(const int* __restrict__ ei) {
    int idx = blockIdx.x * blockDim.x + threadIdx.x;
    if (idx >= Rr * Ee) return;
    int r = idx / Ee, e = idx - r * Ee;
    const int* base = ei + (size_t)r * 2 * Ee;
    atomicAdd(&g_deg_r[r * Nn + base[e]], 1);
    atomicAdd(&g_deg_c[r * Nn + base[Ee + e]], 1);
}
__global__ void k_dinv() {
    int i = blockIdx.x * blockDim.x + threadIdx.x;
    if (i >= Rr * Nn) return;
    g_dinv_r[i] = rsqrtf(fmaxf((float)g_deg_r[i], 1.0f));
    g_dinv_c[i] = rsqrtf(fmaxf((float)g_deg_c[i], 1.0f));
}

// ---- multi-block scan: phase 1 (local exclusive scan + block totals) -------
__global__ __launch_bounds__(1024) void k_scan1() {
    int r = blockIdx.y, b = blockIdx.x;
    int t = threadIdx.x, lane = t & 31, w = t >> 5;
    __shared__ int wsum[32];
    int i0 = b * 4096 + t * 4;
    int v[4], s = 0;
#pragma unroll
    for (int j = 0; j < 4; j++) {
        v[j] = (i0 + j < Nn) ? g_deg_r[r * Nn + i0 + j] : 0;
        s += v[j];
    }
    int x = s;
#pragma unroll
    for (int o = 1; o < 32; o <<= 1) {
        int y = __shfl_up_sync(0xffffffffu, x, o);
        if (lane >= o) x += y;
    }
    if (lane == 31) wsum[w] = x;
    __syncthreads();
    if (w == 0) {
        int s2 = wsum[lane];
#pragma unroll
        for (int o = 1; o < 32; o <<= 1) {
            int y = __shfl_up_sync(0xffffffffu, s2, o);
            if (lane >= o) s2 += y;
        }
        wsum[lane] = s2;
    }
    __syncthreads();
    int woff = (w == 0) ? 0 : wsum[w - 1];
    int run = woff + x - s;
#pragma unroll
    for (int j = 0; j < 4; j++) {
        if (i0 + j < Nn) g_row_ptr[r * (Nn + 1) + i0 + j] = run;
        run += v[j];
    }
    if (t == 1023) g_blksum[r * NBLK + b] = woff + x;
}
__global__ void k_scan2() {
    int t = threadIdx.x, lane = t & 31, w = t >> 5;
    int v = (lane < NBLK) ? g_blksum[w * NBLK + lane] : 0;
    int x = v;
#pragma unroll
    for (int o = 1; o < 32; o <<= 1) {
        int y = __shfl_up_sync(0xffffffffu, x, o);
        if (lane >= o) x += y;
    }
    if (lane < NBLK) g_blksum[w * NBLK + lane] = x - v;
    if (lane == NBLK - 1) g_row_ptr[w * (Nn + 1) + Nn] = x;
}
__global__ __launch_bounds__(1024) void k_scan3() {
    int r = blockIdx.y, b = blockIdx.x;
    int off = g_blksum[r * NBLK + b];
    int i0 = b * 4096 + threadIdx.x * 4;
#pragma unroll
    for (int j = 0; j < 4; j++) {
        int i = i0 + j;
        if (i < Nn) {
            int p = g_row_ptr[r * (Nn + 1) + i] + off;
            g_row_ptr[r * (Nn + 1) + i] = p;
            g_cursor[r * Nn + i] = p;
        }
    }
}

__global__ void k_scatter(const int* __restrict__ ei) {
    int idx = blockIdx.x * blockDim.x + threadIdx.x;
    if (idx >= Rr * Ee) return;
    int r = idx / Ee, e = idx - r * Ee;
    const int* base = ei + (size_t)r * 2 * Ee;
    int row = base[e];
    int col = base[Ee + e];
    int pos = atomicAdd(&g_cursor[r * Nn + row], 1);
    float w = g_dinv_r[r * Nn + row] * g_dinv_c[r * Nn + col];
    g_edge[(size_t)r * Ee + pos] = make_int2(col, __float_as_int(w));
}

// ---------------- fp32 -> fp16 conversion ------------------------------------
__global__ void k_cvt(const float* __restrict__ x, __half* __restrict__ dst) {
    int idx = blockIdx.x * blockDim.x + threadIdx.x;
    const int total = Nn * Hh / 4;
    if (idx >= total) return;
    float4 v = ((const float4*)x)[idx];
    __half2 p0 = __floats2half2_rn(v.x, v.y);
    __half2 p1 = __floats2half2_rn(v.z, v.w);
    uint2 u;
    u.x = *(const uint32_t*)&p0;
    u.y = *(const uint32_t*)&p1;
    ((uint2*)dst)[idx] = u;
}

// ---------------- SpMM: warp per row, fp16 gather, 4-edge pipelined ---------
__device__ __forceinline__ void fma8(float* acc, float w, const uint4& v) {
    const __half2* h = (const __half2*)&v;
    float2 f;
    f = __half22float2(h[0]); acc[0] += w * f.x; acc[1] += w * f.y;
    f = __half22float2(h[1]); acc[2] += w * f.x; acc[3] += w * f.y;
    f = __half22float2(h[2]); acc[4] += w * f.x; acc[5] += w * f.y;
    f = __half22float2(h[3]); acc[6] += w * f.x; acc[7] += w * f.y;
}

__global__ __launch_bounds__(256) void k_spmm(int use_h1) {
    int r = blockIdx.y;
    int n = blockIdx.x * 8 + (threadIdx.x >> 5);
    if (n >= Nn) return;
    int lane = threadIdx.x & 31;
    const uint4* __restrict__ src = (const uint4*)(use_h1 ? g_h1h : g_Xh);
    int beg = g_row_ptr[r * (Nn + 1) + n];
    int end = g_row_ptr[r * (Nn + 1) + n + 1];
    const int2* __restrict__ edges = g_edge + (size_t)r * Ee;
    float acc[8];
#pragma unroll
    for (int j = 0; j < 8; j++) acc[j] = 0.f;

    int e = beg;
    for (; e + 4 <= end; e += 4) {
        int2 d0 = __ldg(edges + e);
        int2 d1 = __ldg(edges + e + 1);
        int2 d2 = __ldg(edges + e + 2);
        int2 d3 = __ldg(edges + e + 3);
        uint4 v0 = __ldg(src + ((size_t)d0.x << 5) + lane);
        uint4 v1 = __ldg(src + ((size_t)d1.x << 5) + lane);
        uint4 v2 = __ldg(src + ((size_t)d2.x << 5) + lane);
        uint4 v3 = __ldg(src + ((size_t)d3.x << 5) + lane);
        fma8(acc, __int_as_float(d0.y), v0);
        fma8(acc, __int_as_float(d1.y), v1);
        fma8(acc, __int_as_float(d2.y), v2);
        fma8(acc, __int_as_float(d3.y), v3);
    }
    for (; e < end; ++e) {
        int2 d = __ldg(edges + e);
        uint4 v = __ldg(src + ((size_t)d.x << 5) + lane);
        fma8(acc, __int_as_float(d.y), v);
    }

    size_t rb = ((size_t)r * Nn + n) * 64;
    split_store4((uint2*)g_Shi + rb + 2 * lane,     (uint2*)g_Slo + rb + 2 * lane,
                 make_float4(acc[0], acc[1], acc[2], acc[3]));
    split_store4((uint2*)g_Shi + rb + 2 * lane + 1, (uint2*)g_Slo + rb + 2 * lane + 1,
                 make_float4(acc[4], acc[5], acc[6], acc[7]));
}

// ---------------- W split+transpose: Bhi[r][n][k] = bf16split(W[r][k][n]) ---
__global__ void k_splitW(const float* __restrict__ W) {
    int idx = blockIdx.x * blockDim.x + threadIdx.x;
    if (idx >= Rr * 256 * 256) return;
    int r = idx >> 16;
    int n = (idx >> 8) & 255;
    int k = idx & 255;
    float w = W[((size_t)r << 16) + ((size_t)k << 8) + n];
    unsigned short h, l;
    split2(w, h, l);
    size_t o = ((size_t)r << 16) + ((size_t)n << 8) + k;
    ((unsigned short*)g_Bhi)[o] = h;
    ((unsigned short*)g_Blo)[o] = l;
}

// ---------------- mma.sync GEMM: H[r] = ReLU(S[r] @ W[r]) -------------------
#define A_STRIDE 72
#define B_STRIDE 264
#define ASZ (128 * A_STRIDE * 2)
#define SM_B_HI 0
#define SM_B_LO (128 * B_STRIDE * 2)
#define SM_A0   (2 * 128 * B_STRIDE * 2)
#define SMEM_GEMM (SM_A0 + 4 * ASZ)

__global__ __launch_bounds__(256) void k_gemm_mma() {
    extern __shared__ char smem[];
    uint32_t sb = smem_to_u32(smem);
    int tid = threadIdx.x, lane = tid & 31, wid = tid >> 5;
    int wm = wid >> 1, wn = wid & 1;
    int r = blockIdx.z, m0 = blockIdx.x * 128, n0 = blockIdx.y * 128;

    {
        const uint4* bh = g_Bhi + ((size_t)(r * 256 + n0)) * 32;
        const uint4* bl = g_Blo + ((size_t)(r * 256 + n0)) * 32;
#pragma unroll
        for (int j = 0; j < 16; j++) {
            int lin = tid + j * 256;
            int row = lin >> 5, ch = lin & 31;
            uint32_t so = row * (B_STRIDE * 2) + ch * 16;
            cp16(sb + SM_B_HI + so, bh + row * 32 + ch, 16);
            cp16(sb + SM_B_LO + so, bl + row * 32 + ch, 16);
        }
    }
    asm volatile("cp.async.commit_group;" ::: "memory");

    auto issueA = [&](int kc) {
        int s = kc & 1;
        uint32_t abase = sb + SM_A0 + s * 2 * ASZ;
#pragma unroll
        for (int j = 0; j < 4; j++) {
            int lin = tid + j * 256;
            int row = lin >> 3, ch = lin & 7;
            int gm = m0 + row;
            int sz = (gm < Nn) ? 16 : 0;
            int gmc = (gm < Nn) ? gm : (Nn - 1);
            size_t gi = ((size_t)r * Nn + gmc) * 32 + kc * 8 + ch;
            uint32_t so = row * (A_STRIDE * 2) + ch * 16;
            cp16(abase + so, g_Shi + gi, sz);
            cp16(abase + ASZ + so, g_Slo + gi, sz);
        }
    };
    issueA(0);
    asm volatile("cp.async.commit_group;" ::: "memory");

    float acc[2][8][4];
#pragma unroll
    for (int a = 0; a < 2; a++)
#pragma unroll
        for (int b = 0; b < 8; b++)
#pragma unroll
            for (int c = 0; c < 4; c++) acc[a][b][c] = 0.f;

    int krow = lane & 15;
    int kof  = (lane >> 4) * 8;

    for (int kc = 0; kc < 4; kc++) {
        if (kc < 3) {
            issueA(kc + 1);
            asm volatile("cp.async.commit_group;" ::: "memory");
            asm volatile("cp.async.wait_group 1;" ::: "memory");
        } else {
            asm volatile("cp.async.wait_group 0;" ::: "memory");
        }
        __syncthreads();

        uint32_t ahb = sb + SM_A0 + (kc & 1) * 2 * ASZ;
        uint32_t alb = ahb + ASZ;
#pragma unroll
        for (int kk = 0; kk < 4; kk++) {
            uint32_t ahi[2][4], alo[2][4], bhi[4][4], blo[4][4];
            uint32_t a_off = (wm * 32 + krow) * (A_STRIDE * 2) + (kk * 16 + kof) * 2;
            ldsm4(ahi[0], ahb + a_off);
            ldsm4(ahi[1], ahb + a_off + 16 * (A_STRIDE * 2));
            ldsm4(alo[0], alb + a_off);
            ldsm4(alo[1], alb + a_off + 16 * (A_STRIDE * 2));
            int kg = kc * 64 + kk * 16 + kof;
#pragma unroll
            for (int nq = 0; nq < 4; nq++) {
                uint32_t b_off = (wn * 64 + nq * 16 + krow) * (B_STRIDE * 2) + kg * 2;
                ldsm4(bhi[nq], sb + SM_B_HI + b_off);
                ldsm4(blo[nq], sb + SM_B_LO + b_off);
            }
#pragma unroll
            for (int mt = 0; mt < 2; mt++) {
#pragma unroll
                for (int nq = 0; nq < 4; nq++) {
                    float* cl = acc[mt][nq * 2];
                    float* ch = acc[mt][nq * 2 + 1];
                    mma16816(cl, ahi[mt], bhi[nq][0], bhi[nq][2]);
                    mma16816(ch, ahi[mt], bhi[nq][1], bhi[nq][3]);
                    mma16816(cl, ahi[mt], blo[nq][0], blo[nq][2]);
                    mma16816(ch, ahi[mt], blo[nq][1], blo[nq][3]);
                    mma16816(cl, alo[mt], bhi[nq][0], bhi[nq][2]);
                    mma16816(ch, alo[mt], bhi[nq][1], bhi[nq][3]);
                }
            }
        }
        __syncthreads();
    }

    int gm_base = m0 + wm * 32 + (lane >> 2);
    int gn_base = n0 + wn * 64 + (lane & 3) * 2;
#pragma unroll
    for (int mt = 0; mt < 2; mt++) {
#pragma unroll
        for (int nn = 0; nn < 8; nn++) {
            float* c = acc[mt][nn];
            int gm = gm_base + mt * 16;
            int gn = gn_base + nn * 8;
            if (gm < Nn) {
                float2 v = make_float2(fmaxf(c[0], 0.f), fmaxf(c[1], 0.f));
                *(float2*)(g_H + ((size_t)r * Nn + gm) * Hh + gn) = v;
            }
            if (gm + 8 < Nn) {
                float2 v = make_float2(fmaxf(c[2], 0.f), fmaxf(c[3], 0.f));
                *(float2*)(g_H + ((size_t)r * Nn + gm + 8) * Hh + gn) = v;
            }
        }
    }
}

// ---------------- layer-1 mean -> fp16 h1 -----------------------------------
__global__ void k_mean() {
    int idx = blockIdx.x * blockDim.x + threadIdx.x;
    const int total = Nn * Hh / 4;
    if (idx >= total) return;
    const float4* h = (const float4*)g_H;
    size_t off = (size_t)Nn * Hh / 4;
    float4 a = h[idx], b = h[idx + off], c = h[idx + 2 * off], d = h[idx + 3 * off];
    float4 m;
    m.x = 0.25f * (a.x + b.x + c.x + d.x);
    m.y = 0.25f * (a.y + b.y + c.y + d.y);
    m.z = 0.25f * (a.z + b.z + c.z + d.z);
    m.w = 0.25f * (a.w + b.w + c.w + d.w);
    __half2 p0 = __floats2half2_rn(m.x, m.y);
    __half2 p1 = __floats2half2_rn(m.z, m.w);
    uint2 u;
    u.x = *(const uint32_t*)&p0;
    u.y = *(const uint32_t*)&p1;
    ((uint2*)g_h1h)[idx] = u;
}

// ---------------- attention + residual fusion + output GEMM -----------------
__global__ __launch_bounds__(256) void k_attn(const float* __restrict__ att_q,
                                              const float* __restrict__ tau_p,
                                              const float* __restrict__ W_out,
                                              const float* __restrict__ b_out,
                                              float* __restrict__ out) {
    int n = blockIdx.x * 8 + (threadIdx.x >> 5);
    if (n >= Nn) return;
    int lane = threadIdx.x & 31;

    float q[8];
#pragma unroll
    for (int k = 0; k < 8; k++) q[k] = att_q[lane + 32 * k];

    float v[4][8];
    float sc[4];
#pragma unroll
    for (int r = 0; r < 4; r++) {
        const float* h = g_H + ((size_t)r * Nn + n) * Hh;
        float s = 0.f;
#pragma unroll
        for (int k = 0; k < 8; k++) {
            v[r][k] = h[lane + 32 * k];
            s += v[r][k] * q[k];
        }
#pragma unroll
        for (int o = 16; o; o >>= 1) s += __shfl_xor_sync(0xffffffffu, s, o);
        sc[r] = s;
    }
    float tc = fminf(fmaxf(tau_p[0], 0.5f), 5.0f);
    float inv = 1.0f / tc;
    float s0 = sc[0] * inv, s1 = sc[1] * inv, s2 = sc[2] * inv, s3 = sc[3] * inv;
    float m = fmaxf(fmaxf(s0, s1), fmaxf(s2, s3));
    float e0 = expf(s0 - m), e1 = expf(s1 - m), e2 = expf(s2 - m), e3 = expf(s3 - m);
    float se = e0 + e1 + e2 + e3;
    float al[4] = {e0 / se, e1 / se, e2 / se, e3 / se};

    float h2[8];
#pragma unroll
    for (int k = 0; k < 8; k++)
        h2[k] = (0.25f + al[0]) * v[0][k] + (0.25f + al[1]) * v[1][k] +
                (0.25f + al[2]) * v[2][k] + (0.25f + al[3]) * v[3][k];

    float acc[16];
#pragma unroll
    for (int c = 0; c < 16; c++) acc[c] = 0.f;
#pragma unroll
    for (int k = 0; k < 8; k++) {
        int idx = lane + 32 * k;
        const float4* wr = (const float4*)(W_out + (size_t)idx * 16);
        float4 w0 = wr[0], w1 = wr[1], w2 = wr[2], w3 = wr[3];
        float hv = h2[k];
        acc[0]  += hv * w0.x; acc[1]  += hv * w0.y; acc[2]  += hv * w0.z; acc[3]  += hv * w0.w;
        acc[4]  += hv * w1.x; acc[5]  += hv * w1.y; acc[6]  += hv * w1.z; acc[7]  += hv * w1.w;
        acc[8]  += hv * w2.x; acc[9]  += hv * w2.y; acc[10] += hv * w2.z; acc[11] += hv * w2.w;
        acc[12] += hv * w3.x; acc[13] += hv * w3.y; acc[14] += hv * w3.z; acc[15] += hv * w3.w;
    }
#pragma unroll
    for (int c = 0; c < 16; c++)
#pragma unroll
        for (int o = 16; o; o >>= 1) acc[c] += __shfl_xor_sync(0xffffffffu, acc[c], o);

    if (lane < 16) {
        float lg = 0.f;
#pragma unroll
        for (int c = 0; c < 16; c++)
            if (lane == c) lg = acc[c];
        out[(size_t)n * Cc + lane] = lg + b_out[lane];
    }
    if (lane < 4) {
        float a = al[0];
        if (lane == 1) a = al[1];
        if (lane == 2) a = al[2];
        if (lane == 3) a = al[3];
        out[(size_t)Nn * Cc + (size_t)n * Rr + lane] = a;
    }
}

// ---------------- launch ----------------------------------------------------
extern "C" void kernel_launch(void* const* d_in, const int* in_sizes, int n_in,
                              void* d_out, int out_size) {
    const float* X     = (const float*)d_in[0];
    const int*   EI    = (const int*)d_in[1];
    const float* W1    = (const float*)d_in[2];
    const float* W2    = (const float*)d_in[3];
    const float* att_q = (const float*)d_in[4];
    const float* tau   = (const float*)d_in[5];
    const float* W_out = (const float*)d_in[6];
    const float* b_out = (const float*)d_in[7];
    float* out = (float*)d_out;
    (void)in_sizes; (void)n_in; (void)out_size;

    cudaFuncSetAttribute(k_gemm_mma, cudaFuncAttributeMaxDynamicSharedMemorySize, SMEM_GEMM);

    // CSR build
    k_zero_deg<<<(Rr * Nn + 255) / 256, 256>>>();
    k_hist<<<(Rr * Ee + 255) / 256, 256>>>(EI);
    k_dinv<<<(Rr * Nn + 255) / 256, 256>>>();
    k_scan1<<<dim3(NBLK, Rr), 1024>>>();
    k_scan2<<<1, 128>>>();
    k_scan3<<<dim3(NBLK, Rr), 1024>>>();
    k_scatter<<<(Rr * Ee + 255) / 256, 256>>>(EI);

    // fp16 copy of X for gathers
    __half* xh;
    cudaGetSymbolAddress((void**)&xh, g_Xh);
    k_cvt<<<(Nn * Hh / 4 + 255) / 256, 256>>>(X, xh);

    dim3 spmm_grid((Nn + 7) / 8, Rr);
    dim3 gemm_grid((Nn + 127) / 128, Hh / 128, Rr);

    // Layer 1
    k_spmm<<<spmm_grid, 256>>>(0);
    k_splitW<<<(Rr * 256 * 256 + 255) / 256, 256>>>(W1);
    k_gemm_mma<<<gemm_grid, 256, SMEM_GEMM>>>();
    k_mean<<<(Nn * Hh / 4 + 255) / 256, 256>>>();

    // Layer 2
    k_spmm<<<spmm_grid, 256>>>(1);
    k_splitW<<<(Rr * 256 * 256 + 255) / 256, 256>>>(W2);
    k_gemm_mma<<<gemm_grid, 256, SMEM_GEMM>>>();

    // Attention + output head
    k_attn<<<(Nn + 7) / 8, 256>>>(att_q, tau, W_out, b_out, out);
}